// round 9
// baseline (speedup 1.0000x reference)
#include <cuda_runtime.h>
#include <cuda_fp16.h>

#define Bsz 1024
#define Tt 128
#define Dd 64
#define Hh 256
#define H4 1024
#define Mrows 8
#define NBLOCKS 128
#define NTHREADS 512
#define KTOT 384
#define RS 68

// ---------------- preprocessed weights (device globals) ----------------
__device__ __half g_lstmW[KTOT * H4];  // fp16 packed [k][n]: k<128 -> lstm_k, else lstm_rk
__device__ float  g_tdhWT[Dd * Hh];    // [k][j] transposed td_h_W (fp32)

__global__ void prep_kernel(const float* __restrict__ td_h_W,
                            const float* __restrict__ lstm_k,
                            const float* __restrict__ lstm_rk) {
    int stride = gridDim.x * blockDim.x;
    int tid = blockIdx.x * blockDim.x + threadIdx.x;
    for (int i = tid; i < KTOT * H4; i += stride) {
        int k = i >> 10;
        float w = (k < 128) ? lstm_k[i] : lstm_rk[i - (128 << 10)];
        g_lstmW[i] = __float2half_rn(w);
    }
    for (int i = tid; i < Dd * Hh; i += stride) {
        int k = i >> 8, j = i & 255;
        g_tdhWT[i] = td_h_W[j * Dd + k];
    }
}

// ---------------- smem layout (floats) ----------------
#define OFF_INPT 0                      // [384][8] k-major: [c_c | m | h]
#define OFF_C    3072                   // [8][256]
#define OFF_DT   5120                   // [64][8]
#define OFF_X    5632                   // [8][RS]
#define OFF_D    6176
#define OFF_GX   7264
#define OFF_XC   8352
#define OFF_M    9440
#define OFF_SCR  9984                   // 8192 floats: PART (A) / Pp partial+act (P8/E)
#define OFF_WH   18176                  // hist_W [256][64]           (16384)
#define OFF_WCT  34560                  // wc_W transposed [64][132]  (8448)
#define OFF_WFT  43008                  // fr_W rows [64][68]         (4352)
#define OFF_WTDX 47360                  // td_x_W^T [64][64]          (4096)
#define SMEM_FLOATS 51456
#define SMEM_BYTES (SMEM_FLOATS * 4)

__device__ __forceinline__ void ffma2(float2& d, const float2& a, const float2& b) {
    asm("fma.rn.f32x2 %0, %1, %2, %0;"
        : "+l"(reinterpret_cast<unsigned long long&>(d))
        : "l"(reinterpret_cast<const unsigned long long&>(a)),
          "l"(reinterpret_cast<const unsigned long long&>(b)));
}
__device__ __forceinline__ float2 dup2(float w) {
    float2 r;
    asm("mov.b64 %0, {%1, %1};"
        : "=l"(reinterpret_cast<unsigned long long&>(r)) : "f"(w));
    return r;
}
__device__ __forceinline__ float sigmoid_fast(float x) {
    return 1.0f / (1.0f + __expf(-x));
}
__device__ __forceinline__ float tanh_fast(float x) {
    float e = __expf(2.0f * x);
    return 1.0f - 2.0f / (e + 1.0f);
}

__global__ void __launch_bounds__(NTHREADS, 1)
rits_main(const float* __restrict__ values,
          const float* __restrict__ masks,
          const float* __restrict__ deltas,
          const float* __restrict__ td_h_b,
          const float* __restrict__ td_x_W,
          const float* __restrict__ td_x_b,
          const float* __restrict__ hist_W,
          const float* __restrict__ hist_b,
          const float* __restrict__ fr_b,
          const float* __restrict__ fr_W,
          const float* __restrict__ wc_W,
          const float* __restrict__ wc_b,
          const float* __restrict__ lstm_b,
          const float* __restrict__ out_W,
          const float* __restrict__ out_b,
          float* __restrict__ y_out,
          float* __restrict__ imp_out) {
    extern __shared__ float sm[];
    const int tid = threadIdx.x;
    const int b0  = blockIdx.x * Mrows;
    const int jj  = tid & 255;
    const int kh  = tid >> 8;
    const int j64 = tid & 63;
    const int r8  = tid >> 6;

    // ---- init: zero state + stage small weights into smem ----
    for (int i = tid; i < Mrows * KTOT; i += NTHREADS) sm[OFF_INPT + i] = 0.0f;
    for (int i = tid; i < Mrows * Hh;  i += NTHREADS) sm[OFF_C + i]    = 0.0f;
    for (int i = tid; i < Hh * Dd; i += NTHREADS) sm[OFF_WH + i] = hist_W[i];
    for (int i = tid; i < 2 * Dd * Dd; i += NTHREADS) {           // wc: [k][j] -> [j][132]
        int k = i >> 6, j = i & 63;
        sm[OFF_WCT + j * 132 + k] = wc_W[i];
    }
    for (int i = tid; i < Dd * Dd; i += NTHREADS) {               // fr rows: [j][68]
        int j = i >> 6, k = i & 63;
        sm[OFF_WFT + j * 68 + k] = fr_W[i];
    }
    for (int i = tid; i < Dd * Dd; i += NTHREADS) {               // tdx^T: [k][j]
        int j = i >> 6, k = i & 63;
        sm[OFF_WTDX + k * Dd + j] = td_x_W[i];
    }

    // hoisted invariants
    const float4 bb     = reinterpret_cast<const float4*>(lstm_b)[jj];
    const float  tdh_bj = td_h_b[jj];
    const float  tdx_bj = td_x_b[j64];
    const float  wc_bj  = wc_b[j64];
    const float  fr_bj  = fr_b[j64];
    const float  hi_bj  = hist_b[j64];
    const uint2* W2base = reinterpret_cast<const uint2*>(g_lstmW) + jj; // 4 halves per col-group
    const float4* A4    = reinterpret_cast<const float4*>(&sm[OFF_INPT]);
    float2* Pp = reinterpret_cast<float2*>(&sm[OFF_SCR]);   // [p][c][jj]

    // ---- t=0 input load + store ----
    {
        int g = (b0 + r8) * (Tt * Dd) + j64;
        float xv = __ldcs(&values[g]);
        float dv = __ldcs(&deltas[g]);
        float mv = __ldcs(&masks[g]);
        sm[OFF_X + r8 * RS + j64] = xv;
        sm[OFF_D + r8 * RS + j64] = dv;
        sm[OFF_DT + j64 * 8 + r8] = dv;
        sm[OFF_M + r8 * RS + j64] = mv;
        sm[OFF_INPT + (Dd + j64) * 8 + r8] = mv;
    }
    __syncthreads();

    float xh_reg = 0.0f, m_reg = 0.0f, x_reg = 0.0f;

    for (int t = 0; t < Tt; t++) {
        const bool pf = (t + 1 < Tt);

        // ---- A: x_h partials (8-way split-K) + gamma_x ----
        {
            int ch = r8;
            float2 a0 = {0, 0}, a1 = a0, a2 = a0, a3 = a0;
            int kb = ch * 32;
#pragma unroll 4
            for (int k = kb; k < kb + 32; k++) {
                float2 wd = dup2(sm[OFF_WH + k * Dd + j64]);
                const float* hp = &sm[OFF_INPT + (2 * Dd + k) * 8];
                float4 h0 = *reinterpret_cast<const float4*>(hp);
                float4 h1 = *reinterpret_cast<const float4*>(hp + 4);
                ffma2(a0, *reinterpret_cast<const float2*>(&h0.x), wd);
                ffma2(a1, *reinterpret_cast<const float2*>(&h0.z), wd);
                ffma2(a2, *reinterpret_cast<const float2*>(&h1.x), wd);
                ffma2(a3, *reinterpret_cast<const float2*>(&h1.z), wd);
            }
            float* pp = &sm[OFF_SCR + ch * (Mrows * RS) + j64];
            pp[0 * RS] = a0.x; pp[1 * RS] = a0.y; pp[2 * RS] = a1.x; pp[3 * RS] = a1.y;
            pp[4 * RS] = a2.x; pp[5 * RS] = a2.y; pp[6 * RS] = a3.x; pp[7 * RS] = a3.y;
        }
        {
            float a = tdx_bj;
            const float* dp = &sm[OFF_D + r8 * RS];
#pragma unroll
            for (int k = 0; k < Dd; k += 4) {
                float4 dv = *reinterpret_cast<const float4*>(dp + k);
                a = fmaf(dv.x, sm[OFF_WTDX + (k + 0) * Dd + j64], a);
                a = fmaf(dv.y, sm[OFF_WTDX + (k + 1) * Dd + j64], a);
                a = fmaf(dv.z, sm[OFF_WTDX + (k + 2) * Dd + j64], a);
                a = fmaf(dv.w, sm[OFF_WTDX + (k + 3) * Dd + j64], a);
            }
            sm[OFF_GX + r8 * RS + j64] = __expf(-fmaxf(a, 0.0f));
        }
        __syncthreads();

        // ---- B: reduce x_h; x_c -> smem; keep xh/m/x in regs ----
        {
            float xh = hi_bj;
#pragma unroll
            for (int ch = 0; ch < 8; ch++) xh += sm[OFF_SCR + ch * (Mrows * RS) + r8 * RS + j64];
            xh_reg = xh;
            m_reg  = sm[OFF_M + r8 * RS + j64];
            x_reg  = sm[OFF_X + r8 * RS + j64];
            sm[OFF_XC + r8 * RS + j64] = m_reg * x_reg + (1.0f - m_reg) * xh;
        }
        __syncthreads();

        // ---- C: alpha + z_h + c_h + c_c (fused) ----
        {
            const float* gp  = &sm[OFF_GX + r8 * RS];
            const float* mp  = &sm[OFF_M + r8 * RS];
            const float* xp  = &sm[OFF_XC + r8 * RS];
            const float* wcT = &sm[OFF_WCT + j64 * 132];
            const float* frT = &sm[OFF_WFT + j64 * 68];
            float a = wc_bj, z = fr_bj;
#pragma unroll
            for (int k = 0; k < Dd; k += 4) {
                float4 wg = *reinterpret_cast<const float4*>(wcT + k);
                float4 gv = *reinterpret_cast<const float4*>(gp + k);
                a = fmaf(gv.x, wg.x, fmaf(gv.y, wg.y, fmaf(gv.z, wg.z, fmaf(gv.w, wg.w, a))));
                float4 wm = *reinterpret_cast<const float4*>(wcT + Dd + k);
                float4 mv = *reinterpret_cast<const float4*>(mp + k);
                a = fmaf(mv.x, wm.x, fmaf(mv.y, wm.y, fmaf(mv.z, wm.z, fmaf(mv.w, wm.w, a))));
                float4 wf = *reinterpret_cast<const float4*>(frT + k);
                float4 xv4 = *reinterpret_cast<const float4*>(xp + k);
                z = fmaf(xv4.x, wf.x, fmaf(xv4.y, wf.y, fmaf(xv4.z, wf.z, fmaf(xv4.w, wf.w, z))));
            }
            float chv = a * z + (1.0f - a) * xh_reg;
            float cc  = m_reg * x_reg + (1.0f - m_reg) * chv;
            sm[OFF_INPT + j64 * 8 + r8] = cc;
            imp_out[(b0 + r8) * (Tt * Dd) + t * Dd + j64] = cc;
        }
        __syncthreads();

        // ---- P8: big GEMM (fp16 weights, rolling prefetch) + input prefetch ----
        {
            float nxv = 0.0f, ndv = 0.0f, nmv = 0.0f;
            if (pf) {
                int g = (b0 + r8) * (Tt * Dd) + (t + 1) * Dd + j64;
                nxv = __ldcs(&values[g]);
                ndv = __ldcs(&deltas[g]);
                nmv = __ldcs(&masks[g]);
            }

            float2 acc[4][4];
            if (kh == 0) {
                const float* bp = reinterpret_cast<const float*>(&bb);
#pragma unroll
                for (int c = 0; c < 4; c++) {
                    float2 b2 = {bp[c], bp[c]};
#pragma unroll
                    for (int p = 0; p < 4; p++) acc[c][p] = b2;
                }
            } else {
#pragma unroll
                for (int c = 0; c < 4; c++)
#pragma unroll
                    for (int p = 0; p < 4; p++) acc[c][p] = make_float2(0.0f, 0.0f);
            }
            const int kb = kh * 192;

            // rolling prefetch of fp16 weights (uint2 = 4 halves)
            uint2 wv[4];
#pragma unroll
            for (int i = 0; i < 4; i++) wv[i] = __ldcg(W2base + (kb + i) * 256);
#pragma unroll 1
            for (int k4 = kb; k4 < kb + 192; k4 += 4) {
                uint2 nv[4];
                int knext = (k4 + 4 < kb + 192) ? (k4 + 4) : kb;
#pragma unroll
                for (int i = 0; i < 4; i++) nv[i] = __ldcg(W2base + (knext + i) * 256);
#pragma unroll
                for (int i = 0; i < 4; i++) {
                    int k = k4 + i;
                    float2 f01 = __half22float2(*reinterpret_cast<const __half2*>(&wv[i].x));
                    float2 f23 = __half22float2(*reinterpret_cast<const __half2*>(&wv[i].y));
                    float2 w0 = dup2(f01.x), w1 = dup2(f01.y);
                    float2 w2 = dup2(f23.x), w3 = dup2(f23.y);
                    float4 a03 = A4[k * 2];
                    float4 a47 = A4[k * 2 + 1];
                    const float2 p0 = *reinterpret_cast<const float2*>(&a03.x);
                    const float2 p1 = *reinterpret_cast<const float2*>(&a03.z);
                    const float2 p2 = *reinterpret_cast<const float2*>(&a47.x);
                    const float2 p3 = *reinterpret_cast<const float2*>(&a47.z);
                    ffma2(acc[0][0], p0, w0); ffma2(acc[0][1], p1, w0);
                    ffma2(acc[0][2], p2, w0); ffma2(acc[0][3], p3, w0);
                    ffma2(acc[1][0], p0, w1); ffma2(acc[1][1], p1, w1);
                    ffma2(acc[1][2], p2, w1); ffma2(acc[1][3], p3, w1);
                    ffma2(acc[2][0], p0, w2); ffma2(acc[2][1], p1, w2);
                    ffma2(acc[2][2], p2, w2); ffma2(acc[2][3], p3, w2);
                    ffma2(acc[3][0], p0, w3); ffma2(acc[3][1], p1, w3);
                    ffma2(acc[3][2], p2, w3); ffma2(acc[3][3], p3, w3);
                }
#pragma unroll
                for (int i = 0; i < 4; i++) wv[i] = nv[i];
            }

            if (kh == 1) {
#pragma unroll
                for (int p = 0; p < 4; p++)
#pragma unroll
                    for (int c = 0; c < 4; c++)
                        Pp[p * 1024 + c * 256 + jj] = acc[c][p];
            }
            __syncthreads();

            // next-step inputs -> smem (GEMM reads of this step are done)
            if (pf) {
                sm[OFF_X + r8 * RS + j64] = nxv;
                sm[OFF_D + r8 * RS + j64] = ndv;
                sm[OFF_DT + j64 * 8 + r8] = ndv;
                sm[OFF_M + r8 * RS + j64] = nmv;
                sm[OFF_INPT + (Dd + j64) * 8 + r8] = nmv;
            }

            if (kh == 0) {
                int gate = jj >> 6;  // warp-uniform
#pragma unroll
                for (int p = 0; p < 4; p++)
#pragma unroll
                    for (int c = 0; c < 4; c++) {
                        float2 q = Pp[p * 1024 + c * 256 + jj];
                        acc[c][p].x += q.x;
                        acc[c][p].y += q.y;
                    }
                if (gate == 2) {
#pragma unroll
                    for (int p = 0; p < 4; p++)
#pragma unroll
                        for (int c = 0; c < 4; c++) {
                            float2 v = {tanh_fast(acc[c][p].x), tanh_fast(acc[c][p].y)};
                            Pp[p * 1024 + c * 256 + jj] = v;
                        }
                } else {
#pragma unroll
                    for (int p = 0; p < 4; p++)
#pragma unroll
                        for (int c = 0; c < 4; c++) {
                            float2 v = {sigmoid_fast(acc[c][p].x), sigmoid_fast(acc[c][p].y)};
                            Pp[p * 1024 + c * 256 + jj] = v;
                        }
                }
            }
            __syncthreads();
        }

        // ---- E: LSTM state update + fused h-decay for step t+1 ----
        {
            int hid = jj;
            int cpart = (hid & 3) * 256 + (hid >> 2);
            float hreg[4];
#pragma unroll
            for (int pp2 = 0; pp2 < 2; pp2++) {
                int p = kh * 2 + pp2;
                float2 iv = Pp[p * 1024 + cpart + 0 * 64];
                float2 fv = Pp[p * 1024 + cpart + 1 * 64];
                float2 gv = Pp[p * 1024 + cpart + 2 * 64];
                float2 ov = Pp[p * 1024 + cpart + 3 * 64];
#pragma unroll
                for (int e = 0; e < 2; e++) {
                    int r = 4 * kh + 2 * pp2 + e;
                    float i_ = e ? iv.y : iv.x;
                    float f_ = e ? fv.y : fv.x;
                    float g_ = e ? gv.y : gv.x;
                    float o_ = e ? ov.y : ov.x;
                    float cn = f_ * sm[OFF_C + r * Hh + hid] + i_ * g_;
                    sm[OFF_C + r * Hh + hid] = cn;
                    hreg[2 * pp2 + e] = o_ * tanh_fast(cn);
                }
            }
            // fused h-decay: gamma_h from d[t+1] (DT updated in P8)
            if (pf) {
                float2 a0 = {tdh_bj, tdh_bj}, a1 = a0;
#pragma unroll 4
                for (int k = 0; k < Dd; k++) {
                    float2 wd = dup2(g_tdhWT[k * Hh + jj]);
                    float4 dv = *reinterpret_cast<const float4*>(&sm[OFF_DT + k * 8 + 4 * kh]);
                    ffma2(a0, *reinterpret_cast<const float2*>(&dv.x), wd);
                    ffma2(a1, *reinterpret_cast<const float2*>(&dv.z), wd);
                }
                hreg[0] *= __expf(-fmaxf(a0.x, 0.0f));
                hreg[1] *= __expf(-fmaxf(a0.y, 0.0f));
                hreg[2] *= __expf(-fmaxf(a1.x, 0.0f));
                hreg[3] *= __expf(-fmaxf(a1.y, 0.0f));
            }
            float4 hv = {hreg[0], hreg[1], hreg[2], hreg[3]};
            *reinterpret_cast<float4*>(&sm[OFF_INPT + (2 * Dd + jj) * 8 + 4 * kh]) = hv;
        }
        __syncthreads();
    }

    // ---- y = h @ out_W + out_b ----
    {
        int w = tid >> 5, lane = tid & 31;
        if (w < Mrows) {
            float s = 0.0f;
            for (int j = lane; j < Hh; j += 32)
                s += sm[OFF_INPT + (2 * Dd + j) * 8 + w] * out_W[j];
#pragma unroll
            for (int o = 16; o > 0; o >>= 1) s += __shfl_down_sync(0xffffffffu, s, o);
            if (lane == 0) y_out[b0 + w] = s + out_b[0];
        }
    }
}

extern "C" void kernel_launch(void* const* d_in, const int* in_sizes, int n_in,
                              void* d_out, int out_size) {
    const float* values  = (const float*)d_in[0];
    const float* masks   = (const float*)d_in[1];
    const float* deltas  = (const float*)d_in[2];
    const float* td_h_W  = (const float*)d_in[3];
    const float* td_h_b  = (const float*)d_in[4];
    const float* td_x_W  = (const float*)d_in[5];
    const float* td_x_b  = (const float*)d_in[6];
    const float* hist_W  = (const float*)d_in[7];
    const float* hist_b  = (const float*)d_in[8];
    const float* fr_W    = (const float*)d_in[9];
    const float* fr_b    = (const float*)d_in[10];
    const float* wc_W    = (const float*)d_in[11];
    const float* wc_b    = (const float*)d_in[12];
    const float* lstm_k  = (const float*)d_in[13];
    const float* lstm_rk = (const float*)d_in[14];
    const float* lstm_b  = (const float*)d_in[15];
    const float* out_W   = (const float*)d_in[16];
    const float* out_b   = (const float*)d_in[17];

    float* y_out   = (float*)d_out;
    float* imp_out = (float*)d_out + Bsz;

    prep_kernel<<<128, 256>>>(td_h_W, lstm_k, lstm_rk);

    cudaFuncSetAttribute(rits_main, cudaFuncAttributeMaxDynamicSharedMemorySize, SMEM_BYTES);
    rits_main<<<NBLOCKS, NTHREADS, SMEM_BYTES>>>(
        values, masks, deltas,
        td_h_b, td_x_W, td_x_b, hist_W, hist_b, fr_b, fr_W, wc_W, wc_b,
        lstm_b, out_W, out_b, y_out, imp_out);
}

// round 12
// speedup vs baseline: 1.1638x; 1.1638x over previous
#include <cuda_runtime.h>

#define Bsz 1024
#define Tt 128
#define Dd 64
#define Hh 256
#define H4 1024
#define Mrows 8
#define NBLOCKS 128
#define NTHREADS 512
#define KTOT 384
#define RS 68

// ---------------- preprocessed weights (device globals) ----------------
__device__ float g_lstmW[KTOT * H4];  // fp32 packed [k][n]: k<128 -> lstm_k, else lstm_rk
__device__ float g_tdhWT[Dd * Hh];    // [k][j] transposed td_h_W

__global__ void prep_kernel(const float* __restrict__ td_h_W,
                            const float* __restrict__ lstm_k,
                            const float* __restrict__ lstm_rk) {
    int stride = gridDim.x * blockDim.x;
    int tid = blockIdx.x * blockDim.x + threadIdx.x;
    for (int i = tid; i < KTOT * H4; i += stride) {
        int k = i >> 10;
        g_lstmW[i] = (k < 128) ? lstm_k[i] : lstm_rk[i - (128 << 10)];
    }
    for (int i = tid; i < Dd * Hh; i += stride) {
        int k = i >> 8, j = i & 255;
        g_tdhWT[i] = td_h_W[j * Dd + k];
    }
}

// ---------------- smem layout (floats) ----------------
#define OFF_INPT 0                      // [384][8] k-major: [c_c | m | h]
#define OFF_C    3072                   // [8][256]
#define OFF_DT   5120                   // [64][8]
#define OFF_X    5632                   // [8][RS]
#define OFF_D    6176
#define OFF_GX   7264
#define OFF_XC   8352
#define OFF_M    9440
#define OFF_SCR  9984                   // 8192 floats: PART (A) / Pp partial+act (P8/E)
#define OFF_WH   18176                  // hist_W [256][64]           (16384)
#define OFF_WCT  34560                  // wc_W transposed [64][132]  (8448)
#define OFF_WFT  43008                  // fr_W rows [64][68]         (4352)
#define OFF_WTDX 47360                  // td_x_W^T [64][64]          (4096)
#define SMEM_FLOATS 51456
#define SMEM_BYTES (SMEM_FLOATS * 4)

__device__ __forceinline__ void ffma2(float2& d, const float2& a, const float2& b) {
    asm("fma.rn.f32x2 %0, %1, %2, %0;"
        : "+l"(reinterpret_cast<unsigned long long&>(d))
        : "l"(reinterpret_cast<const unsigned long long&>(a)),
          "l"(reinterpret_cast<const unsigned long long&>(b)));
}
__device__ __forceinline__ float2 dup2(float w) {
    float2 r;
    asm("mov.b64 %0, {%1, %1};"
        : "=l"(reinterpret_cast<unsigned long long&>(r)) : "f"(w));
    return r;
}
// HW tanh: 1 MUFU op (vs 2 for EX2+RCP chains)
__device__ __forceinline__ float tanh_hw(float x) {
    float r;
    asm("tanh.approx.f32 %0, %1;" : "=f"(r) : "f"(x));
    return r;
}
__device__ __forceinline__ float sigmoid_hw(float x) {
    return fmaf(0.5f, tanh_hw(0.5f * x), 0.5f);
}

__global__ void __launch_bounds__(NTHREADS, 1)
rits_main(const float* __restrict__ values,
          const float* __restrict__ masks,
          const float* __restrict__ deltas,
          const float* __restrict__ td_h_b,
          const float* __restrict__ td_x_W,
          const float* __restrict__ td_x_b,
          const float* __restrict__ hist_W,
          const float* __restrict__ hist_b,
          const float* __restrict__ fr_b,
          const float* __restrict__ fr_W,
          const float* __restrict__ wc_W,
          const float* __restrict__ wc_b,
          const float* __restrict__ lstm_b,
          const float* __restrict__ out_W,
          const float* __restrict__ out_b,
          float* __restrict__ y_out,
          float* __restrict__ imp_out) {
    extern __shared__ float sm[];
    const int tid = threadIdx.x;
    const int b0  = blockIdx.x * Mrows;
    const int jj  = tid & 255;
    const int kh  = tid >> 8;
    const int j64 = tid & 63;
    const int r8  = tid >> 6;

    // ---- init: zero state + stage small weights into smem ----
    for (int i = tid; i < Mrows * KTOT; i += NTHREADS) sm[OFF_INPT + i] = 0.0f;
    for (int i = tid; i < Mrows * Hh;  i += NTHREADS) sm[OFF_C + i]    = 0.0f;
    for (int i = tid; i < Hh * Dd; i += NTHREADS) sm[OFF_WH + i] = hist_W[i];
    for (int i = tid; i < 2 * Dd * Dd; i += NTHREADS) {           // wc: [k][j] -> [j][132]
        int k = i >> 6, j = i & 63;
        sm[OFF_WCT + j * 132 + k] = wc_W[i];
    }
    for (int i = tid; i < Dd * Dd; i += NTHREADS) {               // fr rows: [j][68]
        int j = i >> 6, k = i & 63;
        sm[OFF_WFT + j * 68 + k] = fr_W[i];
    }
    for (int i = tid; i < Dd * Dd; i += NTHREADS) {               // tdx^T: [k][j]
        int j = i >> 6, k = i & 63;
        sm[OFF_WTDX + k * Dd + j] = td_x_W[i];
    }

    // hoisted invariants
    const float4 bb     = reinterpret_cast<const float4*>(lstm_b)[jj];
    const float  tdh_bj = td_h_b[jj];
    const float  tdx_bj = td_x_b[j64];
    const float  wc_bj  = wc_b[j64];
    const float  fr_bj  = fr_b[j64];
    const float  hi_bj  = hist_b[j64];
    const float4* W4base = reinterpret_cast<const float4*>(g_lstmW) + jj;
    const float4* A4     = reinterpret_cast<const float4*>(&sm[OFF_INPT]);
    float2* Pp = reinterpret_cast<float2*>(&sm[OFF_SCR]);   // [p][c][jj]

    // ---- t=0 input load + store ----
    {
        int g = (b0 + r8) * (Tt * Dd) + j64;
        float xv = __ldcs(&values[g]);
        float dv = __ldcs(&deltas[g]);
        float mv = __ldcs(&masks[g]);
        sm[OFF_X + r8 * RS + j64] = xv;
        sm[OFF_D + r8 * RS + j64] = dv;
        sm[OFF_DT + j64 * 8 + r8] = dv;
        sm[OFF_M + r8 * RS + j64] = mv;
        sm[OFF_INPT + (Dd + j64) * 8 + r8] = mv;
    }
    __syncthreads();

    float xh_reg = 0.0f, m_reg = 0.0f, x_reg = 0.0f;

    for (int t = 0; t < Tt; t++) {
        const bool pf = (t + 1 < Tt);

        // ---- A: x_h partials (8-way split-K) + gamma_x ----
        {
            int ch = r8;
            float2 a0 = {0, 0}, a1 = a0, a2 = a0, a3 = a0;
            int kb = ch * 32;
#pragma unroll 4
            for (int k = kb; k < kb + 32; k++) {
                float2 wd = dup2(sm[OFF_WH + k * Dd + j64]);
                const float* hp = &sm[OFF_INPT + (2 * Dd + k) * 8];
                float4 h0 = *reinterpret_cast<const float4*>(hp);
                float4 h1 = *reinterpret_cast<const float4*>(hp + 4);
                ffma2(a0, *reinterpret_cast<const float2*>(&h0.x), wd);
                ffma2(a1, *reinterpret_cast<const float2*>(&h0.z), wd);
                ffma2(a2, *reinterpret_cast<const float2*>(&h1.x), wd);
                ffma2(a3, *reinterpret_cast<const float2*>(&h1.z), wd);
            }
            float* pp = &sm[OFF_SCR + ch * (Mrows * RS) + j64];
            pp[0 * RS] = a0.x; pp[1 * RS] = a0.y; pp[2 * RS] = a1.x; pp[3 * RS] = a1.y;
            pp[4 * RS] = a2.x; pp[5 * RS] = a2.y; pp[6 * RS] = a3.x; pp[7 * RS] = a3.y;
        }
        {
            float a = tdx_bj;
            const float* dp = &sm[OFF_D + r8 * RS];
#pragma unroll
            for (int k = 0; k < Dd; k += 4) {
                float4 dv = *reinterpret_cast<const float4*>(dp + k);
                a = fmaf(dv.x, sm[OFF_WTDX + (k + 0) * Dd + j64], a);
                a = fmaf(dv.y, sm[OFF_WTDX + (k + 1) * Dd + j64], a);
                a = fmaf(dv.z, sm[OFF_WTDX + (k + 2) * Dd + j64], a);
                a = fmaf(dv.w, sm[OFF_WTDX + (k + 3) * Dd + j64], a);
            }
            sm[OFF_GX + r8 * RS + j64] = __expf(-fmaxf(a, 0.0f));
        }
        __syncthreads();

        // ---- B: reduce x_h; x_c -> smem; keep xh/m/x in regs ----
        {
            float xh = hi_bj;
#pragma unroll
            for (int ch = 0; ch < 8; ch++) xh += sm[OFF_SCR + ch * (Mrows * RS) + r8 * RS + j64];
            xh_reg = xh;
            m_reg  = sm[OFF_M + r8 * RS + j64];
            x_reg  = sm[OFF_X + r8 * RS + j64];
            sm[OFF_XC + r8 * RS + j64] = m_reg * x_reg + (1.0f - m_reg) * xh;
        }
        __syncthreads();

        // ---- C: alpha + z_h + c_h + c_c (fused) ----
        {
            const float* gp  = &sm[OFF_GX + r8 * RS];
            const float* mp  = &sm[OFF_M + r8 * RS];
            const float* xp  = &sm[OFF_XC + r8 * RS];
            const float* wcT = &sm[OFF_WCT + j64 * 132];
            const float* frT = &sm[OFF_WFT + j64 * 68];
            float a = wc_bj, z = fr_bj;
#pragma unroll
            for (int k = 0; k < Dd; k += 4) {
                float4 wg = *reinterpret_cast<const float4*>(wcT + k);
                float4 gv = *reinterpret_cast<const float4*>(gp + k);
                a = fmaf(gv.x, wg.x, fmaf(gv.y, wg.y, fmaf(gv.z, wg.z, fmaf(gv.w, wg.w, a))));
                float4 wm = *reinterpret_cast<const float4*>(wcT + Dd + k);
                float4 mv = *reinterpret_cast<const float4*>(mp + k);
                a = fmaf(mv.x, wm.x, fmaf(mv.y, wm.y, fmaf(mv.z, wm.z, fmaf(mv.w, wm.w, a))));
                float4 wf = *reinterpret_cast<const float4*>(frT + k);
                float4 xv4 = *reinterpret_cast<const float4*>(xp + k);
                z = fmaf(xv4.x, wf.x, fmaf(xv4.y, wf.y, fmaf(xv4.z, wf.z, fmaf(xv4.w, wf.w, z))));
            }
            float chv = a * z + (1.0f - a) * xh_reg;
            float cc  = m_reg * x_reg + (1.0f - m_reg) * chv;
            sm[OFF_INPT + j64 * 8 + r8] = cc;
            imp_out[(b0 + r8) * (Tt * Dd) + t * Dd + j64] = cc;
        }
        __syncthreads();

        // ---- P8: big GEMM (fp32 weights, rolling prefetch) + input prefetch ----
        {
            float nxv = 0.0f, ndv = 0.0f, nmv = 0.0f;
            if (pf) {
                int g = (b0 + r8) * (Tt * Dd) + (t + 1) * Dd + j64;
                nxv = __ldcs(&values[g]);
                ndv = __ldcs(&deltas[g]);
                nmv = __ldcs(&masks[g]);
            }

            float2 acc[4][4];
            if (kh == 0) {
                const float* bp = reinterpret_cast<const float*>(&bb);
#pragma unroll
                for (int c = 0; c < 4; c++) {
                    float2 b2 = {bp[c], bp[c]};
#pragma unroll
                    for (int p = 0; p < 4; p++) acc[c][p] = b2;
                }
            } else {
#pragma unroll
                for (int c = 0; c < 4; c++)
#pragma unroll
                    for (int p = 0; p < 4; p++) acc[c][p] = make_float2(0.0f, 0.0f);
            }
            const int kb = kh * 192;

            float4 wv[4];
#pragma unroll
            for (int i = 0; i < 4; i++) wv[i] = __ldcg(W4base + (kb + i) * 256);
#pragma unroll 1
            for (int k4 = kb; k4 < kb + 192; k4 += 4) {
                float4 nv[4];
                int knext = (k4 + 4 < kb + 192) ? (k4 + 4) : kb;
#pragma unroll
                for (int i = 0; i < 4; i++) nv[i] = __ldcg(W4base + (knext + i) * 256);
#pragma unroll
                for (int i = 0; i < 4; i++) {
                    int k = k4 + i;
                    float4 w = wv[i];
                    float2 w0 = dup2(w.x), w1 = dup2(w.y), w2 = dup2(w.z), w3 = dup2(w.w);
                    float4 a03 = A4[k * 2];
                    float4 a47 = A4[k * 2 + 1];
                    const float2 p0 = *reinterpret_cast<const float2*>(&a03.x);
                    const float2 p1 = *reinterpret_cast<const float2*>(&a03.z);
                    const float2 p2 = *reinterpret_cast<const float2*>(&a47.x);
                    const float2 p3 = *reinterpret_cast<const float2*>(&a47.z);
                    ffma2(acc[0][0], p0, w0); ffma2(acc[0][1], p1, w0);
                    ffma2(acc[0][2], p2, w0); ffma2(acc[0][3], p3, w0);
                    ffma2(acc[1][0], p0, w1); ffma2(acc[1][1], p1, w1);
                    ffma2(acc[1][2], p2, w1); ffma2(acc[1][3], p3, w1);
                    ffma2(acc[2][0], p0, w2); ffma2(acc[2][1], p1, w2);
                    ffma2(acc[2][2], p2, w2); ffma2(acc[2][3], p3, w2);
                    ffma2(acc[3][0], p0, w3); ffma2(acc[3][1], p1, w3);
                    ffma2(acc[3][2], p2, w3); ffma2(acc[3][3], p3, w3);
                }
#pragma unroll
                for (int i = 0; i < 4; i++) wv[i] = nv[i];
            }

            if (kh == 1) {
#pragma unroll
                for (int p = 0; p < 4; p++)
#pragma unroll
                    for (int c = 0; c < 4; c++)
                        Pp[p * 1024 + c * 256 + jj] = acc[c][p];
            }
            __syncthreads();

            // next-step inputs -> smem (GEMM reads of this step are done)
            if (pf) {
                sm[OFF_X + r8 * RS + j64] = nxv;
                sm[OFF_D + r8 * RS + j64] = ndv;
                sm[OFF_DT + j64 * 8 + r8] = ndv;
                sm[OFF_M + r8 * RS + j64] = nmv;
                sm[OFF_INPT + (Dd + j64) * 8 + r8] = nmv;
            }

            if (kh == 0) {
                int gate = jj >> 6;  // warp-uniform
#pragma unroll
                for (int p = 0; p < 4; p++)
#pragma unroll
                    for (int c = 0; c < 4; c++) {
                        float2 q = Pp[p * 1024 + c * 256 + jj];
                        acc[c][p].x += q.x;
                        acc[c][p].y += q.y;
                    }
                if (gate == 2) {
#pragma unroll
                    for (int p = 0; p < 4; p++)
#pragma unroll
                        for (int c = 0; c < 4; c++) {
                            float2 v = {tanh_hw(acc[c][p].x), tanh_hw(acc[c][p].y)};
                            Pp[p * 1024 + c * 256 + jj] = v;
                        }
                } else {
#pragma unroll
                    for (int p = 0; p < 4; p++)
#pragma unroll
                        for (int c = 0; c < 4; c++) {
                            float2 v = {sigmoid_hw(acc[c][p].x), sigmoid_hw(acc[c][p].y)};
                            Pp[p * 1024 + c * 256 + jj] = v;
                        }
                }
            }
            __syncthreads();
        }

        // ---- E: LSTM state update + fused h-decay for step t+1 ----
        {
            int hid = jj;
            int cpart = (hid & 3) * 256 + (hid >> 2);
            float hreg[4];
#pragma unroll
            for (int pp2 = 0; pp2 < 2; pp2++) {
                int p = kh * 2 + pp2;
                float2 iv = Pp[p * 1024 + cpart + 0 * 64];
                float2 fv = Pp[p * 1024 + cpart + 1 * 64];
                float2 gv = Pp[p * 1024 + cpart + 2 * 64];
                float2 ov = Pp[p * 1024 + cpart + 3 * 64];
#pragma unroll
                for (int e = 0; e < 2; e++) {
                    int r = 4 * kh + 2 * pp2 + e;
                    float i_ = e ? iv.y : iv.x;
                    float f_ = e ? fv.y : fv.x;
                    float g_ = e ? gv.y : gv.x;
                    float o_ = e ? ov.y : ov.x;
                    float cn = f_ * sm[OFF_C + r * Hh + hid] + i_ * g_;
                    sm[OFF_C + r * Hh + hid] = cn;
                    hreg[2 * pp2 + e] = o_ * tanh_hw(cn);
                }
            }
            // fused h-decay: gamma_h from d[t+1] (DT updated in P8)
            if (pf) {
                float2 a0 = {tdh_bj, tdh_bj}, a1 = a0;
#pragma unroll 4
                for (int k = 0; k < Dd; k++) {
                    float2 wd = dup2(g_tdhWT[k * Hh + jj]);
                    float4 dv = *reinterpret_cast<const float4*>(&sm[OFF_DT + k * 8 + 4 * kh]);
                    ffma2(a0, *reinterpret_cast<const float2*>(&dv.x), wd);
                    ffma2(a1, *reinterpret_cast<const float2*>(&dv.z), wd);
                }
                hreg[0] *= __expf(-fmaxf(a0.x, 0.0f));
                hreg[1] *= __expf(-fmaxf(a0.y, 0.0f));
                hreg[2] *= __expf(-fmaxf(a1.x, 0.0f));
                hreg[3] *= __expf(-fmaxf(a1.y, 0.0f));
            }
            float4 hv = {hreg[0], hreg[1], hreg[2], hreg[3]};
            *reinterpret_cast<float4*>(&sm[OFF_INPT + (2 * Dd + jj) * 8 + 4 * kh]) = hv;
        }
        __syncthreads();
    }

    // ---- y = h @ out_W + out_b ----
    {
        int w = tid >> 5, lane = tid & 31;
        if (w < Mrows) {
            float s = 0.0f;
            for (int j = lane; j < Hh; j += 32)
                s += sm[OFF_INPT + (2 * Dd + j) * 8 + w] * out_W[j];
#pragma unroll
            for (int o = 16; o > 0; o >>= 1) s += __shfl_down_sync(0xffffffffu, s, o);
            if (lane == 0) y_out[b0 + w] = s + out_b[0];
        }
    }
}

extern "C" void kernel_launch(void* const* d_in, const int* in_sizes, int n_in,
                              void* d_out, int out_size) {
    const float* values  = (const float*)d_in[0];
    const float* masks   = (const float*)d_in[1];
    const float* deltas  = (const float*)d_in[2];
    const float* td_h_W  = (const float*)d_in[3];
    const float* td_h_b  = (const float*)d_in[4];
    const float* td_x_W  = (const float*)d_in[5];
    const float* td_x_b  = (const float*)d_in[6];
    const float* hist_W  = (const float*)d_in[7];
    const float* hist_b  = (const float*)d_in[8];
    const float* fr_W    = (const float*)d_in[9];
    const float* fr_b    = (const float*)d_in[10];
    const float* wc_W    = (const float*)d_in[11];
    const float* wc_b    = (const float*)d_in[12];
    const float* lstm_k  = (const float*)d_in[13];
    const float* lstm_rk = (const float*)d_in[14];
    const float* lstm_b  = (const float*)d_in[15];
    const float* out_W   = (const float*)d_in[16];
    const float* out_b   = (const float*)d_in[17];

    float* y_out   = (float*)d_out;
    float* imp_out = (float*)d_out + Bsz;

    prep_kernel<<<128, 256>>>(td_h_W, lstm_k, lstm_rk);

    cudaFuncSetAttribute(rits_main, cudaFuncAttributeMaxDynamicSharedMemorySize, SMEM_BYTES);
    rits_main<<<NBLOCKS, NTHREADS, SMEM_BYTES>>>(
        values, masks, deltas,
        td_h_b, td_x_W, td_x_b, hist_W, hist_b, fr_b, fr_W, wc_W, wc_b,
        lstm_b, out_W, out_b, y_out, imp_out);
}